// round 15
// baseline (speedup 1.0000x reference)
#include <cuda_runtime.h>
#include <math.h>
#include <stdint.h>

// ---------------------------------------------------------------------------
// Problem constants
// ---------------------------------------------------------------------------
#define B_   64
#define S_   512
#define F_   128
#define U_   512
#define SIGDIM 16512            // F + F*F
#define NB_  8
#define LN_EPS 1e-3f
#define NS_BIG 86               // splits for big GEMM: 86 * 192 = 16512
#define BG_KT  12               // k-tiles (of 16) per split: 12*16 = 192

typedef unsigned long long u64;

// ---------------------------------------------------------------------------
// Device scratch
// ---------------------------------------------------------------------------
__device__ float g_sig  [B_ * SIGDIM];
__device__ float g_M    [B_ * F_ * F_];
__device__ float g_part [2 * NS_BIG * B_ * U_];   // 22.5 MB split partials
__device__ float g_attn [B_ * U_];
__device__ float g_PQ   [B_ * 1152];
__device__ float g_Wc   [1152 * U_];
__device__ float g_cur  [B_ * U_];
__device__ float g_gates[4 * B_ * U_];

struct P4 { const float* p[4]; };
struct O4 { float* p[4]; };

// ---------------------------------------------------------------------------
// Helpers
// ---------------------------------------------------------------------------
__device__ __forceinline__ float fsigmoid(float x) { return 1.0f / (1.0f + __expf(-x)); }

__device__ __forceinline__ void cp16(void* s, const void* g) {
    uint32_t a = (uint32_t)__cvta_generic_to_shared(s);
    asm volatile("cp.async.cg.shared.global [%0], [%1], 16;" :: "r"(a), "l"(g));
}
__device__ __forceinline__ void cp_commit() { asm volatile("cp.async.commit_group;"); }
template<int N> __device__ __forceinline__ void cp_wait() {
    asm volatile("cp.async.wait_group %0;" :: "n"(N));
}

// packed f32x2 helpers (Blackwell): 2 fp32 FMAs per issue slot
__device__ __forceinline__ u64 pack2(float a) {
    u64 r; asm("mov.b64 %0, {%1, %1};" : "=l"(r) : "f"(a)); return r;
}
__device__ __forceinline__ void fma2(u64& d, u64 a, u64 b) {
    asm("fma.rn.f32x2 %0, %1, %2, %0;" : "+l"(d) : "l"(a), "l"(b));
}

__device__ __forceinline__ float blockReduceSum(float v, float* smem) {
    int lane = threadIdx.x & 31, w = threadIdx.x >> 5;
    #pragma unroll
    for (int o = 16; o > 0; o >>= 1) v += __shfl_xor_sync(0xffffffffu, v, o);
    if (lane == 0) smem[w] = v;
    __syncthreads();
    int nw = blockDim.x >> 5;
    float r = (threadIdx.x < nw) ? smem[threadIdx.x] : 0.0f;
    if (w == 0) {
        #pragma unroll
        for (int o = 16; o > 0; o >>= 1) r += __shfl_xor_sync(0xffffffffu, r, o);
        if (lane == 0) smem[0] = r;
    }
    __syncthreads();
    float out = smem[0];
    __syncthreads();
    return out;
}

__device__ __forceinline__ float blockReduceMax(float v, float* smem) {
    int lane = threadIdx.x & 31, w = threadIdx.x >> 5;
    #pragma unroll
    for (int o = 16; o > 0; o >>= 1) v = fmaxf(v, __shfl_xor_sync(0xffffffffu, v, o));
    if (lane == 0) smem[w] = v;
    __syncthreads();
    int nw = blockDim.x >> 5;
    float r = (threadIdx.x < nw) ? smem[threadIdx.x] : -INFINITY;
    if (w == 0) {
        #pragma unroll
        for (int o = 16; o > 0; o >>= 1) r = fmaxf(r, __shfl_xor_sync(0xffffffffu, r, o));
        if (lane == 0) smem[0] = r;
    }
    __syncthreads();
    float out = smem[0];
    __syncthreads();
    return out;
}

// ---------------------------------------------------------------------------
// K1: fused init: gate biases, zeros (cur/PQ/M), base_w->Wc, s1,
//     PLUS spline_w transpose (blocks >= initBlocks).
// ---------------------------------------------------------------------------
#define NBIAS_  (4 * B_ * U_)                       // 4 gate bias fills
#define NINIT_  (NBIAS_ + B_*U_ + B_*1152 + B_*F_*F_ + F_*U_ + B_*F_)
#define INIT_BLOCKS ((NINIT_ + 255) / 256)

__global__ void __launch_bounds__(256) init_fused_kernel(
        const float* bf, const float* bi, const float* bc, const float* bo,
        const float* base_w, const float* __restrict__ spline_w,
        const float* __restrict__ x, const float* __restrict__ tk) {
    if (blockIdx.x >= INIT_BLOCKS) {
        // spline transpose tile: Wc[128+kk][u] = spline_w[u][kk]
        __shared__ float tile[32][33];
        int bid = blockIdx.x - INIT_BLOCKS;          // 0..511
        int kk0 = (bid & 31) * 32, u0 = (bid >> 5) * 32;
        int tx = threadIdx.x & 31, ty = threadIdx.x >> 5;
        #pragma unroll
        for (int a = 0; a < 32; a += 8)
            tile[ty + a][tx] = spline_w[(u0 + ty + a) * 1024 + kk0 + tx];
        __syncthreads();
        #pragma unroll
        for (int a = 0; a < 32; a += 8)
            g_Wc[(F_ + kk0 + ty + a) * U_ + u0 + tx] = tile[tx][ty + a];
        return;
    }
    int idx = blockIdx.x * blockDim.x + threadIdx.x;
    if (idx < NBIAS_) {
        int which = idx >> 15;
        int r = idx & 32767;
        int u = r & (U_ - 1);
        const float* bb = (which == 0) ? bf : (which == 1) ? bi : (which == 2) ? bc : bo;
        g_gates[which * 32768 + r] = bb[u];
        return;
    }
    int r = idx - NBIAS_;
    if (r < B_ * U_) { g_cur[r] = 0.0f; return; }
    r -= B_ * U_;
    if (r < B_ * 1152) { g_PQ[r] = 0.0f; return; }
    r -= B_ * 1152;
    if (r < B_ * F_ * F_) { g_M[r] = 0.0f; return; }
    r -= B_ * F_ * F_;
    if (r < F_ * U_) { g_Wc[r] = base_w[r]; return; }
    r -= F_ * U_;
    if (r < B_ * F_) {
        int b = r >> 7, c = r & 127;
        g_sig[b * SIGDIM + c] = tk[S_ - 1] * x[(b * S_ + S_ - 1) * F_ + c]
                              - tk[0]      * x[b * S_ * F_ + c];
    }
}

// ---------------------------------------------------------------------------
// K2: M[b,i,j] = sum_t (tk_t*tk_{t+1}) x_t[i] x_{t+1}[j]
// 8 splits of 64 products; cp.async double-buffered; f32x2 inner loop.
// ---------------------------------------------------------------------------
__global__ void __launch_bounds__(256) sig2_kernel(const float* __restrict__ x,
                                                   const float* __restrict__ tk) {
    int b = blockIdx.y;
    int tBegin = blockIdx.x * 64;
    __shared__ float Xs[2][33][128];
    __shared__ float sprod[64];

    int tid = threadIdx.x;

    if (tid < 64) {
        int t = tBegin + tid;
        sprod[tid] = (t < S_ - 1) ? tk[t] * tk[t + 1] : 0.0f;
    }

#define S2_ISSUE(SS) do { \
        int rowBase = (SS) * 32; int buf_ = (SS) & 1; \
        _Pragma("unroll") \
        for (int it = 0; it < 5; it++) { \
            int e = tid + it * 256; \
            if (e < 33 * 32) { \
                int r = e >> 5, c4 = (e & 31) << 2; \
                int gr = tBegin + rowBase + r; \
                if (gr > S_ - 1) gr = S_ - 1; \
                cp16(&Xs[buf_][r][c4], &x[((size_t)b * S_ + gr) * F_ + c4]); \
            } \
        } \
    } while (0)

#define S2_COMPUTE(TT) do { \
        int buf_ = (TT) & 1; int kb = (TT) * 32; \
        _Pragma("unroll") \
        for (int kk = 0; kk < 32; kk++) { \
            float s_ = sprod[kb + kk]; \
            ulonglong2 q0 = *(const ulonglong2*)&Xs[buf_][kk + 1][tx * 8]; \
            ulonglong2 q1 = *(const ulonglong2*)&Xs[buf_][kk + 1][tx * 8 + 4]; \
            u64 d2[4] = {q0.x, q0.y, q1.x, q1.y}; \
            float4 alo = *(const float4*)&Xs[buf_][kk][ty * 8]; \
            float4 ahi = *(const float4*)&Xs[buf_][kk][ty * 8 + 4]; \
            float a8[8] = {alo.x * s_, alo.y * s_, alo.z * s_, alo.w * s_, \
                           ahi.x * s_, ahi.y * s_, ahi.z * s_, ahi.w * s_}; \
            _Pragma("unroll") \
            for (int i = 0; i < 8; i++) { \
                u64 ap = pack2(a8[i]); \
                fma2(acc2[i][0], ap, d2[0]); \
                fma2(acc2[i][1], ap, d2[1]); \
                fma2(acc2[i][2], ap, d2[2]); \
                fma2(acc2[i][3], ap, d2[3]); \
            } \
        } \
    } while (0)

    S2_ISSUE(0); cp_commit();
    S2_ISSUE(1); cp_commit();

    int tx = tid & 15, ty = tid >> 4;
    u64 acc2[8][4];
    #pragma unroll
    for (int i = 0; i < 8; i++)
        #pragma unroll
        for (int j = 0; j < 4; j++) acc2[i][j] = 0ULL;

    cp_wait<1>(); __syncthreads();
    S2_COMPUTE(0);
    cp_wait<0>(); __syncthreads();
    S2_COMPUTE(1);

    float* Mb = g_M + b * F_ * F_;
    #pragma unroll
    for (int i = 0; i < 8; i++) {
        const float* af = (const float*)&acc2[i][0];
        #pragma unroll
        for (int j = 0; j < 8; j++)
            atomicAdd(&Mb[(ty * 8 + i) * F_ + tx * 8 + j], af[j]);
    }
#undef S2_ISSUE
#undef S2_COMPUTE
}

// ---------------------------------------------------------------------------
// K3: sig epilogue (tiled): s2 = 0.5(M - M^T) + 0.5 wL(x)wL + 0.5 w0(x)w0 - w0(x)wL
// ---------------------------------------------------------------------------
__global__ void __launch_bounds__(256) sig_epi_kernel(const float* __restrict__ x,
                                                      const float* __restrict__ tk) {
    int b = blockIdx.z;
    int i0 = blockIdx.y * 32, j0 = blockIdx.x * 32;
    __shared__ float tji[32][33];
    __shared__ float w0i_s[32], wLi_s[32], w0j_s[32], wLj_s[32];

    int tx = threadIdx.x & 31, ty = threadIdx.x >> 5;
    const float* Mb = g_M + b * F_ * F_;
    #pragma unroll
    for (int a = 0; a < 32; a += 8)
        tji[ty + a][tx] = Mb[(j0 + ty + a) * F_ + i0 + tx];
    if (threadIdx.x < 32) {
        float tk0 = tk[0], tkL = tk[S_ - 1];
        const float* xb = x + b * S_ * F_;
        w0i_s[tx] = tk0 * xb[i0 + tx];
        wLi_s[tx] = tkL * xb[(S_ - 1) * F_ + i0 + tx];
        w0j_s[tx] = tk0 * xb[j0 + tx];
        wLj_s[tx] = tkL * xb[(S_ - 1) * F_ + j0 + tx];
    }
    __syncthreads();

    float* dst = g_sig + b * SIGDIM + F_;
    float w0j = w0j_s[tx], wLj = wLj_s[tx];
    #pragma unroll
    for (int a = 0; a < 32; a += 8) {
        int i = i0 + ty + a, j = j0 + tx;
        float mij = Mb[i * F_ + j];
        float mji = tji[tx][ty + a];
        float w0i = w0i_s[ty + a], wLi = wLi_s[ty + a];
        dst[i * F_ + j] = 0.5f * (mij - mji)
                        + 0.5f * wLi * wLj + 0.5f * w0i * w0j - w0i * wLj;
    }
}

// ---------------------------------------------------------------------------
// K4: BIG GEMM, cp.async 4-stage, f32x2 inner (round-13 body, no swizzle).
// grid (4, 86, 2). 128 threads, 64x128 tile, 8x8/thread, zero atomics.
// ---------------------------------------------------------------------------
__global__ void __launch_bounds__(128) bgemm(const float* __restrict__ A,
                                             const float* __restrict__ Bw0,
                                             const float* __restrict__ Bw1,
                                             float* __restrict__ Cpart) {
    const float* __restrict__ Bw = blockIdx.z ? Bw1 : Bw0;
    int n0 = blockIdx.x * 128;
    int kBegin = blockIdx.y * (BG_KT * 16);

    __shared__ float As[4][64][16];        // [stage][m][kk]
    __shared__ float Bs[4][16][128];       // [stage][kk][n]

    int tid = threadIdx.x;
    int ty = tid >> 4, tx = tid & 15;      // rows ty*8.., cols tx*8..

    u64 acc2[8][4];
    #pragma unroll
    for (int i = 0; i < 8; i++)
        #pragma unroll
        for (int j = 0; j < 4; j++) acc2[i][j] = 0ULL;

#define BG_ISSUE(T) do { \
        int k0_ = kBegin + (T) * 16; int buf_ = (T) & 3; \
        _Pragma("unroll") \
        for (int it = 0; it < 2; it++) { \
            int e = tid + it * 128; \
            int m_ = e >> 2, kq_ = (e & 3) << 2; \
            cp16(&As[buf_][m_][kq_], &A[m_ * SIGDIM + k0_ + kq_]); \
        } \
        _Pragma("unroll") \
        for (int it = 0; it < 4; it++) { \
            int e = tid + it * 128; \
            int kk_ = e >> 5, nq_ = (e & 31) << 2; \
            cp16(&Bs[buf_][kk_][nq_], &Bw[(k0_ + kk_) * U_ + n0 + nq_]); \
        } \
    } while (0)

    BG_ISSUE(0); cp_commit();
    BG_ISSUE(1); cp_commit();
    BG_ISSUE(2); cp_commit();

    for (int t = 0; t < BG_KT; t++) {
        cp_wait<2>();
        __syncthreads();
        int buf = t & 3;
        #pragma unroll
        for (int kk = 0; kk < 16; kk++) {
            ulonglong2 q0 = *(const ulonglong2*)&Bs[buf][kk][tx * 8];
            ulonglong2 q1 = *(const ulonglong2*)&Bs[buf][kk][tx * 8 + 4];
            u64 b2[4] = {q0.x, q0.y, q1.x, q1.y};
            #pragma unroll
            for (int i = 0; i < 8; i++) {
                u64 ap = pack2(As[buf][ty * 8 + i][kk]);
                fma2(acc2[i][0], ap, b2[0]);
                fma2(acc2[i][1], ap, b2[1]);
                fma2(acc2[i][2], ap, b2[2]);
                fma2(acc2[i][3], ap, b2[3]);
            }
        }
        if (t + 3 < BG_KT) BG_ISSUE(t + 3);
        cp_commit();
    }

    float* dst = Cpart + ((size_t)(blockIdx.z * NS_BIG + blockIdx.y) * 64 + ty * 8) * U_
               + n0 + tx * 8;
    #pragma unroll
    for (int i = 0; i < 8; i++) {
        *(float4*)&dst[i * U_]     = *(const float4*)&acc2[i][0];
        *(float4*)&dst[i * U_ + 4] = *(const float4*)&acc2[i][2];
    }
#undef BG_ISSUE
}

// ---------------------------------------------------------------------------
// K5: FUSED GRN: per-batch-row block (64 blocks x 512 threads).
// reduce partials(+b1/bs) -> elu -> @w2+b2 -> @w3/@w4 -> glu -> LN -> softmax.
// ---------------------------------------------------------------------------
__global__ void __launch_bounds__(512) grn_fused(
        const float* __restrict__ b1, const float* __restrict__ bsk,
        const float* __restrict__ b2, const float* __restrict__ w2,
        const float* __restrict__ b3, const float* __restrict__ w3,
        const float* __restrict__ b4, const float* __restrict__ w4,
        const float* __restrict__ gamma, const float* __restrict__ beta) {
    __shared__ float eluz1[512], yskip_s[512], h2s[512];
    __shared__ float red[32];
    int b = blockIdx.x, u = threadIdx.x;

    // 1) reduce the 86 split partials for row b (both projections)
    float s0 = b1[u], s1v = bsk[u];
    const float* base0 = g_part + (size_t)b * U_ + u;
    #pragma unroll 2
    for (int k = 0; k < NS_BIG; k++) {
        s0  += base0[(size_t)k * (B_ * U_)];
        s1v += base0[(size_t)(NS_BIG + k) * (B_ * U_)];
    }
    eluz1[u] = (s0 > 0.f) ? s0 : (__expf(s0) - 1.f);
    yskip_s[u] = s1v;
    __syncthreads();

    // 2) h2 = elu(z1) @ w2 + b2
    float acc = b2[u];
    #pragma unroll 4
    for (int k = 0; k < U_; k++) acc = fmaf(eluz1[k], w2[k * U_ + u], acc);
    h2s[u] = acc;
    __syncthreads();

    // 3) g3 = h2@w3+b3, g4 = h2@w4+b4
    float a3 = b3[u], a4 = b4[u];
    #pragma unroll 4
    for (int k = 0; k < U_; k++) {
        float h = h2s[k];
        a3 = fmaf(h, w3[k * U_ + u], a3);
        a4 = fmaf(h, w4[k * U_ + u], a4);
    }

    // 4) glu + LN + softmax
    float v = yskip_s[u] + fsigmoid(a3) * a4;
    float mu = blockReduceSum(v, red) * (1.0f / (float)U_);
    float d = v - mu;
    float var = blockReduceSum(d * d, red) * (1.0f / (float)U_);
    float yn = d * rsqrtf(var + LN_EPS) * gamma[u] + beta[u];
    float mx = blockReduceMax(yn, red);
    float e = __expf(yn - mx);
    float s = blockReduceSum(e, red);
    g_attn[b * U_ + u] = e / s;
}

// ---------------------------------------------------------------------------
// K6: P[b,f] = sum_s attn*silu(w), Q[b,f,k] = sum_s attn*bspl_k(w)
// ---------------------------------------------------------------------------
__global__ void __launch_bounds__(128) pq_kernel(const float* __restrict__ x,
                                                 const float* __restrict__ tk) {
    int b = blockIdx.x, chunk = blockIdx.y;
    int f = threadIdx.x;
    int s0 = chunk * 32;

    __shared__ float att_s[32], tk_s[32];
    if (f < 32) {
        att_s[f] = g_attn[b * U_ + s0 + f];
        tk_s[f]  = tk[s0 + f];
    }
    __syncthreads();

    float accP = 0.0f, accQ[8];
    #pragma unroll
    for (int k = 0; k < 8; k++) accQ[k] = 0.0f;

    const float* xb = x + (b * S_ + s0) * F_;
    #pragma unroll 2
    for (int si = 0; si < 32; si++) {
        float att = att_s[si];
        float xw = tk_s[si] * xb[si * F_ + f];
        float th;
        asm("tanh.approx.f32 %0, %1;" : "=f"(th) : "f"(0.5f * xw));
        float sg = fmaf(0.5f, th, 0.5f);
        accP = fmaf(att, xw * sg, accP);
        float c = fmaf(2.5f, xw, 3.5f);
        #pragma unroll
        for (int k = 0; k < 8; k++) {
            float a = fabsf(c - (float)k);
            float a2 = a * a;
            float m = 2.0f - a;
            float p1 = fmaf(fmaf(0.5f, a, -1.0f), a2, 0.66666667f);
            float p2 = m * m * m * (1.0f / 6.0f);
            float v = (a < 1.0f) ? p1 : ((a < 2.0f) ? p2 : 0.0f);
            accQ[k] = fmaf(att, v, accQ[k]);
        }
    }
    atomicAdd(&g_PQ[b * 1152 + f], accP);
    #pragma unroll
    for (int k = 0; k < 8; k++)
        atomicAdd(&g_PQ[b * 1152 + 128 + f * 8 + k], accQ[k]);
}

// ---------------------------------------------------------------------------
// K7: generic small GEMM, M=64, N-tile 128, double-buffered, f32x2 inner.
// ---------------------------------------------------------------------------
__global__ void __launch_bounds__(128) gemm64(
    const float* __restrict__ A, int lda, float ascale,
    const float* __restrict__ A2, int lda2, int kHalf,
    int K, int kChunk,
    P4 Bset, int ldb, O4 Cset, int ldc)
{
    int z = blockIdx.z;
    const float* __restrict__ Bw = Bset.p[z];
    int n0 = blockIdx.x * 128;
    int kBegin = blockIdx.y * kChunk;
    int kEnd = min(K, kBegin + kChunk);

    __shared__ float As[2][16][68];
    __shared__ float Bs[2][16][128];

    int tid = threadIdx.x;
    int tx = tid & 15, ty = tid >> 4;
    int am = tid >> 2;
    int akq = (tid & 3) << 2;
    int bkk = tid >> 5;
    int bnq = (tid & 31) << 2;

    float4 aR[2], bR[4];

#define GLOAD(K0) do { \
        _Pragma("unroll") \
        for (int it = 0; it < 2; it++) { \
            int m = am + it * 32; \
            int k = (K0) + akq; \
            float4 v = make_float4(0.f, 0.f, 0.f, 0.f); \
            if (k < kEnd) { \
                if (k < kHalf) { \
                    v = *(const float4*)&A[m * lda + k]; \
                    v.x *= ascale; v.y *= ascale; v.z *= ascale; v.w *= ascale; \
                } else { \
                    v = *(const float4*)&A2[m * lda2 + (k - kHalf)]; \
                } \
            } \
            aR[it] = v; \
        } \
        _Pragma("unroll") \
        for (int it = 0; it < 4; it++) { \
            int k = (K0) + bkk + it * 4; \
            float4 v = make_float4(0.f, 0.f, 0.f, 0.f); \
            if (k < kEnd) v = *(const float4*)&Bw[k * ldb + n0 + bnq]; \
            bR[it] = v; \
        } \
    } while (0)

#define GSTORE(BUF) do { \
        _Pragma("unroll") \
        for (int it = 0; it < 2; it++) { \
            int m = am + it * 32; \
            As[BUF][akq + 0][m] = aR[it].x; As[BUF][akq + 1][m] = aR[it].y; \
            As[BUF][akq + 2][m] = aR[it].z; As[BUF][akq + 3][m] = aR[it].w; \
        } \
        _Pragma("unroll") \
        for (int it = 0; it < 4; it++) { \
            *(float4*)&Bs[BUF][bkk + it * 4][bnq] = bR[it]; \
        } \
    } while (0)

    u64 acc2[8][4];
    #pragma unroll
    for (int i = 0; i < 8; i++)
        #pragma unroll
        for (int j = 0; j < 4; j++) acc2[i][j] = 0ULL;

    GLOAD(kBegin);
    GSTORE(0);
    __syncthreads();

    int buf = 0;
    for (int k0 = kBegin; k0 < kEnd; k0 += 16) {
        bool nxt = (k0 + 16) < kEnd;
        if (nxt) GLOAD(k0 + 16);
        #pragma unroll
        for (int kk = 0; kk < 16; kk++) {
            ulonglong2 q0 = *(const ulonglong2*)&Bs[buf][kk][tx * 8];
            ulonglong2 q1 = *(const ulonglong2*)&Bs[buf][kk][tx * 8 + 4];
            u64 b2[4] = {q0.x, q0.y, q1.x, q1.y};
            float4 alo = *(const float4*)&As[buf][kk][ty * 8];
            float4 ahi = *(const float4*)&As[buf][kk][ty * 8 + 4];
            float a8[8] = {alo.x, alo.y, alo.z, alo.w, ahi.x, ahi.y, ahi.z, ahi.w};
            #pragma unroll
            for (int i = 0; i < 8; i++) {
                u64 ap = pack2(a8[i]);
                fma2(acc2[i][0], ap, b2[0]);
                fma2(acc2[i][1], ap, b2[1]);
                fma2(acc2[i][2], ap, b2[2]);
                fma2(acc2[i][3], ap, b2[3]);
            }
        }
        if (nxt) GSTORE(buf ^ 1);
        __syncthreads();
        buf ^= 1;
    }
    float* C = Cset.p[z];
    #pragma unroll
    for (int i = 0; i < 8; i++) {
        const float* af = (const float*)&acc2[i][0];
        #pragma unroll
        for (int j = 0; j < 8; j++)
            atomicAdd(&C[(ty * 8 + i) * ldc + n0 + tx * 8 + j], af[j]);
    }
#undef GLOAD
#undef GSTORE
}

// ---------------------------------------------------------------------------
// K8: LSTM elementwise -> out = [h_new | c_new]
// ---------------------------------------------------------------------------
__global__ void final_kernel(const float* __restrict__ c_prev, float* __restrict__ out) {
    int idx = blockIdx.x * blockDim.x + threadIdx.x;
    if (idx >= B_ * U_) return;
    float f = fsigmoid(g_gates[idx]);
    float i = fsigmoid(g_gates[32768 + idx]);
    float cand = tanhf(g_gates[65536 + idx]);
    float o = fsigmoid(g_gates[98304 + idx]);
    float c = f * c_prev[idx] + i * cand;
    float h = o * tanhf(c);
    out[idx] = h;
    out[B_ * U_ + idx] = c;
}

// ---------------------------------------------------------------------------
// Host launcher
// ---------------------------------------------------------------------------
extern "C" void kernel_launch(void* const* d_in, const int* in_sizes, int n_in,
                              void* d_out, int out_size) {
    const float* x        = (const float*)d_in[0];
    const float* h_prev   = (const float*)d_in[1];
    const float* c_prev   = (const float*)d_in[2];
    const float* tk       = (const float*)d_in[3];
    const float* base_w   = (const float*)d_in[4];
    const float* spline_w = (const float*)d_in[5];
    const float* w1       = (const float*)d_in[6];
    const float* b1       = (const float*)d_in[7];
    const float* w2       = (const float*)d_in[8];
    const float* b2       = (const float*)d_in[9];
    const float* w3       = (const float*)d_in[10];
    const float* b3       = (const float*)d_in[11];
    const float* w4       = (const float*)d_in[12];
    const float* b4       = (const float*)d_in[13];
    const float* ws       = (const float*)d_in[14];
    const float* bsk      = (const float*)d_in[15];
    const float* gamma    = (const float*)d_in[16];
    const float* beta     = (const float*)d_in[17];
    const float* wf       = (const float*)d_in[18];
    const float* bf       = (const float*)d_in[19];
    const float* wi       = (const float*)d_in[20];
    const float* bi       = (const float*)d_in[21];
    const float* wc       = (const float*)d_in[22];
    const float* bc       = (const float*)d_in[23];
    const float* wo       = (const float*)d_in[24];
    const float* bo       = (const float*)d_in[25];
    float* out = (float*)d_out;

    float *p_sig, *p_PQ, *p_Wc, *p_cur, *p_gates, *p_part;
    cudaGetSymbolAddress((void**)&p_sig,   g_sig);
    cudaGetSymbolAddress((void**)&p_PQ,    g_PQ);
    cudaGetSymbolAddress((void**)&p_Wc,    g_Wc);
    cudaGetSymbolAddress((void**)&p_cur,   g_cur);
    cudaGetSymbolAddress((void**)&p_gates, g_gates);
    cudaGetSymbolAddress((void**)&p_part,  g_part);

    // (1) fused init: biases/zeros/base_w->Wc/s1 + spline transpose
    init_fused_kernel<<<INIT_BLOCKS + 512, 256>>>(bf, bi, bc, bo, base_w, spline_w, x, tk);
    // (2) signature level-2 (8 splits, cp.async, f32x2)
    sig2_kernel<<<dim3(8, B_), 256>>>(x, tk);
    // (3) signature epilogue
    sig_epi_kernel<<<dim3(4, 4, B_), 256>>>(x, tk);
    // (4) BIG fused sig projections (round-13 body) -> partials
    bgemm<<<dim3(4, NS_BIG, 2), 128>>>(p_sig, w1, ws, p_part);
    // (5) FUSED GRN: reduce + h2 + g3/g4 + glu + LN + softmax -> attn
    grn_fused<<<B_, 512>>>(b1, bsk, b2, w2, b3, w3, b4, w4, gamma, beta);
    // (6) attention-weighted KAN reductions
    pq_kernel<<<dim3(B_, 16), 128>>>(x, tk);
    // (7) current = PQ @ Wc
    {
        P4 Bb; Bb.p[0] = p_Wc; Bb.p[1] = p_Wc; Bb.p[2] = p_Wc; Bb.p[3] = p_Wc;
        O4 Cb; Cb.p[0] = p_cur; Cb.p[1] = p_cur; Cb.p[2] = p_cur; Cb.p[3] = p_cur;
        gemm64<<<dim3(4, 8, 1), 128>>>(p_PQ, 1152, 1.0f, p_PQ, 1152, 1152,
                                       1152, 144, Bb, U_, Cb, U_);
    }
    // (8) LSTM gates: A = [cur/S , h_prev]; 4 gates fused
    {
        P4 Bb; Bb.p[0] = wf; Bb.p[1] = wi; Bb.p[2] = wc; Bb.p[3] = wo;
        O4 Cb; Cb.p[0] = p_gates; Cb.p[1] = p_gates + 32768;
        Cb.p[2] = p_gates + 65536; Cb.p[3] = p_gates + 98304;
        gemm64<<<dim3(4, 8, 4), 128>>>(p_cur, U_, 1.0f / (float)S_, h_prev, U_, U_,
                                       2 * U_, 128, Bb, U_, Cb, U_);
    }
    // (9) LSTM elementwise
    final_kernel<<<(B_ * U_ + 255) / 256, 256>>>(c_prev, out);
}

// round 16
// speedup vs baseline: 1.4085x; 1.4085x over previous
#include <cuda_runtime.h>
#include <math.h>
#include <stdint.h>

// ---------------------------------------------------------------------------
// Problem constants
// ---------------------------------------------------------------------------
#define B_   64
#define S_   512
#define F_   128
#define U_   512
#define SIGDIM 16512            // F + F*F
#define NB_  8
#define LN_EPS 1e-3f
#define NS_BIG 86               // splits for big GEMM: 86 * 192 = 16512
#define BG_KT  12               // k-tiles (of 16) per split: 12*16 = 192

typedef unsigned long long u64;

// ---------------------------------------------------------------------------
// Device scratch
// ---------------------------------------------------------------------------
__device__ float g_sig  [B_ * SIGDIM];
__device__ float g_M    [B_ * F_ * F_];
__device__ float g_part [2 * NS_BIG * B_ * U_];   // 22.5 MB split partials
__device__ float g_z1   [B_ * U_];
__device__ float g_yskip[B_ * U_];
__device__ float g_h2   [B_ * U_];
__device__ float g_g3   [B_ * U_];
__device__ float g_g4   [B_ * U_];
__device__ float g_attn [B_ * U_];
__device__ float g_PQ   [B_ * 1152];
__device__ float g_Wc   [1152 * U_];
__device__ float g_cur  [B_ * U_];
__device__ float g_gates[4 * B_ * U_];

struct P4 { const float* p[4]; };
struct O4 { float* p[4]; };

// ---------------------------------------------------------------------------
// Helpers
// ---------------------------------------------------------------------------
__device__ __forceinline__ float fsigmoid(float x) { return 1.0f / (1.0f + __expf(-x)); }

__device__ __forceinline__ void cp16(void* s, const void* g) {
    uint32_t a = (uint32_t)__cvta_generic_to_shared(s);
    asm volatile("cp.async.cg.shared.global [%0], [%1], 16;" :: "r"(a), "l"(g));
}
__device__ __forceinline__ void cp_commit() { asm volatile("cp.async.commit_group;"); }
template<int N> __device__ __forceinline__ void cp_wait() {
    asm volatile("cp.async.wait_group %0;" :: "n"(N));
}

// packed f32x2 helpers (Blackwell): 2 fp32 FMAs per issue slot
__device__ __forceinline__ u64 pack2(float a) {
    u64 r; asm("mov.b64 %0, {%1, %1};" : "=l"(r) : "f"(a)); return r;
}
__device__ __forceinline__ void fma2(u64& d, u64 a, u64 b) {
    asm("fma.rn.f32x2 %0, %1, %2, %0;" : "+l"(d) : "l"(a), "l"(b));
}

__device__ __forceinline__ float blockReduceSum(float v, float* smem) {
    int lane = threadIdx.x & 31, w = threadIdx.x >> 5;
    #pragma unroll
    for (int o = 16; o > 0; o >>= 1) v += __shfl_xor_sync(0xffffffffu, v, o);
    if (lane == 0) smem[w] = v;
    __syncthreads();
    int nw = blockDim.x >> 5;
    float r = (threadIdx.x < nw) ? smem[threadIdx.x] : 0.0f;
    if (w == 0) {
        #pragma unroll
        for (int o = 16; o > 0; o >>= 1) r += __shfl_xor_sync(0xffffffffu, r, o);
        if (lane == 0) smem[0] = r;
    }
    __syncthreads();
    float out = smem[0];
    __syncthreads();
    return out;
}

__device__ __forceinline__ float blockReduceMax(float v, float* smem) {
    int lane = threadIdx.x & 31, w = threadIdx.x >> 5;
    #pragma unroll
    for (int o = 16; o > 0; o >>= 1) v = fmaxf(v, __shfl_xor_sync(0xffffffffu, v, o));
    if (lane == 0) smem[w] = v;
    __syncthreads();
    int nw = blockDim.x >> 5;
    float r = (threadIdx.x < nw) ? smem[threadIdx.x] : -INFINITY;
    if (w == 0) {
        #pragma unroll
        for (int o = 16; o > 0; o >>= 1) r = fmaxf(r, __shfl_xor_sync(0xffffffffu, r, o));
        if (lane == 0) smem[0] = r;
    }
    __syncthreads();
    float out = smem[0];
    __syncthreads();
    return out;
}

// ---------------------------------------------------------------------------
// K1: fused init: biases (h2,g3,g4,gates), zeros (cur/PQ/M), base_w->Wc, s1,
//     PLUS spline_w transpose tiles (blocks >= INIT_BLOCKS).
// ---------------------------------------------------------------------------
#define NBIAS_  (7 * B_ * U_)
#define NINIT_  (NBIAS_ + B_*U_ + B_*1152 + B_*F_*F_ + F_*U_ + B_*F_)
#define INIT_BLOCKS ((NINIT_ + 255) / 256)

__global__ void __launch_bounds__(256) init_fused_kernel(
        const float* b2, const float* b3, const float* b4,
        const float* bf, const float* bi, const float* bc, const float* bo,
        const float* base_w, const float* __restrict__ spline_w,
        const float* __restrict__ x, const float* __restrict__ tk) {
    if (blockIdx.x >= INIT_BLOCKS) {
        // spline transpose tile: Wc[128+kk][u] = spline_w[u][kk]
        __shared__ float tile[32][33];
        int bid = blockIdx.x - INIT_BLOCKS;          // 0..511
        int kk0 = (bid & 31) * 32, u0 = (bid >> 5) * 32;
        int tx = threadIdx.x & 31, ty = threadIdx.x >> 5;
        #pragma unroll
        for (int a = 0; a < 32; a += 8)
            tile[ty + a][tx] = spline_w[(u0 + ty + a) * 1024 + kk0 + tx];
        __syncthreads();
        #pragma unroll
        for (int a = 0; a < 32; a += 8)
            g_Wc[(F_ + kk0 + ty + a) * U_ + u0 + tx] = tile[tx][ty + a];
        return;
    }
    int idx = blockIdx.x * blockDim.x + threadIdx.x;
    if (idx < NBIAS_) {
        int which = idx >> 15;
        int r = idx & 32767;
        int u = r & (U_ - 1);
        float v; float* dst;
        switch (which) {
            case 0: dst = g_h2;            v = b2[u];  break;
            case 1: dst = g_g3;            v = b3[u];  break;
            case 2: dst = g_g4;            v = b4[u];  break;
            case 3: dst = g_gates;         v = bf[u];  break;
            case 4: dst = g_gates + 32768; v = bi[u];  break;
            case 5: dst = g_gates + 65536; v = bc[u];  break;
            default: dst = g_gates + 98304; v = bo[u]; break;
        }
        dst[r] = v;
        return;
    }
    int r = idx - NBIAS_;
    if (r < B_ * U_) { g_cur[r] = 0.0f; return; }
    r -= B_ * U_;
    if (r < B_ * 1152) { g_PQ[r] = 0.0f; return; }
    r -= B_ * 1152;
    if (r < B_ * F_ * F_) { g_M[r] = 0.0f; return; }
    r -= B_ * F_ * F_;
    if (r < F_ * U_) { g_Wc[r] = base_w[r]; return; }
    r -= F_ * U_;
    if (r < B_ * F_) {
        int b = r >> 7, c = r & 127;
        g_sig[b * SIGDIM + c] = tk[S_ - 1] * x[(b * S_ + S_ - 1) * F_ + c]
                              - tk[0]      * x[b * S_ * F_ + c];
    }
}

// ---------------------------------------------------------------------------
// K2: M[b,i,j] = sum_t (tk_t*tk_{t+1}) x_t[i] x_{t+1}[j]
// 8 splits of 64 products; cp.async double-buffered; f32x2 inner loop.
// ---------------------------------------------------------------------------
__global__ void __launch_bounds__(256) sig2_kernel(const float* __restrict__ x,
                                                   const float* __restrict__ tk) {
    int b = blockIdx.y;
    int tBegin = blockIdx.x * 64;
    __shared__ float Xs[2][33][128];
    __shared__ float sprod[64];

    int tid = threadIdx.x;

    if (tid < 64) {
        int t = tBegin + tid;
        sprod[tid] = (t < S_ - 1) ? tk[t] * tk[t + 1] : 0.0f;
    }

#define S2_ISSUE(SS) do { \
        int rowBase = (SS) * 32; int buf_ = (SS) & 1; \
        _Pragma("unroll") \
        for (int it = 0; it < 5; it++) { \
            int e = tid + it * 256; \
            if (e < 33 * 32) { \
                int r = e >> 5, c4 = (e & 31) << 2; \
                int gr = tBegin + rowBase + r; \
                if (gr > S_ - 1) gr = S_ - 1; \
                cp16(&Xs[buf_][r][c4], &x[((size_t)b * S_ + gr) * F_ + c4]); \
            } \
        } \
    } while (0)

#define S2_COMPUTE(TT) do { \
        int buf_ = (TT) & 1; int kb = (TT) * 32; \
        _Pragma("unroll") \
        for (int kk = 0; kk < 32; kk++) { \
            float s_ = sprod[kb + kk]; \
            ulonglong2 q0 = *(const ulonglong2*)&Xs[buf_][kk + 1][tx * 8]; \
            ulonglong2 q1 = *(const ulonglong2*)&Xs[buf_][kk + 1][tx * 8 + 4]; \
            u64 d2[4] = {q0.x, q0.y, q1.x, q1.y}; \
            float4 alo = *(const float4*)&Xs[buf_][kk][ty * 8]; \
            float4 ahi = *(const float4*)&Xs[buf_][kk][ty * 8 + 4]; \
            float a8[8] = {alo.x * s_, alo.y * s_, alo.z * s_, alo.w * s_, \
                           ahi.x * s_, ahi.y * s_, ahi.z * s_, ahi.w * s_}; \
            _Pragma("unroll") \
            for (int i = 0; i < 8; i++) { \
                u64 ap = pack2(a8[i]); \
                fma2(acc2[i][0], ap, d2[0]); \
                fma2(acc2[i][1], ap, d2[1]); \
                fma2(acc2[i][2], ap, d2[2]); \
                fma2(acc2[i][3], ap, d2[3]); \
            } \
        } \
    } while (0)

    S2_ISSUE(0); cp_commit();
    S2_ISSUE(1); cp_commit();

    int tx = tid & 15, ty = tid >> 4;
    u64 acc2[8][4];
    #pragma unroll
    for (int i = 0; i < 8; i++)
        #pragma unroll
        for (int j = 0; j < 4; j++) acc2[i][j] = 0ULL;

    cp_wait<1>(); __syncthreads();
    S2_COMPUTE(0);
    cp_wait<0>(); __syncthreads();
    S2_COMPUTE(1);

    float* Mb = g_M + b * F_ * F_;
    #pragma unroll
    for (int i = 0; i < 8; i++) {
        const float* af = (const float*)&acc2[i][0];
        #pragma unroll
        for (int j = 0; j < 8; j++)
            atomicAdd(&Mb[(ty * 8 + i) * F_ + tx * 8 + j], af[j]);
    }
#undef S2_ISSUE
#undef S2_COMPUTE
}

// ---------------------------------------------------------------------------
// K3: sig epilogue (tiled): s2 = 0.5(M - M^T) + 0.5 wL(x)wL + 0.5 w0(x)w0 - w0(x)wL
// ---------------------------------------------------------------------------
__global__ void __launch_bounds__(256) sig_epi_kernel(const float* __restrict__ x,
                                                      const float* __restrict__ tk) {
    int b = blockIdx.z;
    int i0 = blockIdx.y * 32, j0 = blockIdx.x * 32;
    __shared__ float tji[32][33];
    __shared__ float w0i_s[32], wLi_s[32], w0j_s[32], wLj_s[32];

    int tx = threadIdx.x & 31, ty = threadIdx.x >> 5;
    const float* Mb = g_M + b * F_ * F_;
    #pragma unroll
    for (int a = 0; a < 32; a += 8)
        tji[ty + a][tx] = Mb[(j0 + ty + a) * F_ + i0 + tx];
    if (threadIdx.x < 32) {
        float tk0 = tk[0], tkL = tk[S_ - 1];
        const float* xb = x + b * S_ * F_;
        w0i_s[tx] = tk0 * xb[i0 + tx];
        wLi_s[tx] = tkL * xb[(S_ - 1) * F_ + i0 + tx];
        w0j_s[tx] = tk0 * xb[j0 + tx];
        wLj_s[tx] = tkL * xb[(S_ - 1) * F_ + j0 + tx];
    }
    __syncthreads();

    float* dst = g_sig + b * SIGDIM + F_;
    float w0j = w0j_s[tx], wLj = wLj_s[tx];
    #pragma unroll
    for (int a = 0; a < 32; a += 8) {
        int i = i0 + ty + a, j = j0 + tx;
        float mij = Mb[i * F_ + j];
        float mji = tji[tx][ty + a];
        float w0i = w0i_s[ty + a], wLi = wLi_s[ty + a];
        dst[i * F_ + j] = 0.5f * (mij - mji)
                        + 0.5f * wLi * wLj + 0.5f * w0i * w0j - w0i * wLj;
    }
}

// ---------------------------------------------------------------------------
// K4: BIG GEMM, cp.async 4-stage, f32x2 inner with pair-k LDS64 A-broadcasts.
// grid (4, 86, 2). 128 threads, 64x128 tile, 8x8/thread, zero atomics.
// ---------------------------------------------------------------------------
__global__ void __launch_bounds__(128) bgemm(const float* __restrict__ A,
                                             const float* __restrict__ Bw0,
                                             const float* __restrict__ Bw1,
                                             float* __restrict__ Cpart) {
    const float* __restrict__ Bw = blockIdx.z ? Bw1 : Bw0;
    int n0 = blockIdx.x * 128;
    int kBegin = blockIdx.y * (BG_KT * 16);

    __shared__ float As[4][64][16];        // [stage][m][kk]
    __shared__ float Bs[4][16][128];       // [stage][kk][n]

    int tid = threadIdx.x;
    int ty = tid >> 4, tx = tid & 15;      // rows ty*8.., cols tx*8..

    u64 acc2[8][4];
    #pragma unroll
    for (int i = 0; i < 8; i++)
        #pragma unroll
        for (int j = 0; j < 4; j++) acc2[i][j] = 0ULL;

#define BG_ISSUE(T) do { \
        int k0_ = kBegin + (T) * 16; int buf_ = (T) & 3; \
        _Pragma("unroll") \
        for (int it = 0; it < 2; it++) { \
            int e = tid + it * 128; \
            int m_ = e >> 2, kq_ = (e & 3) << 2; \
            cp16(&As[buf_][m_][kq_], &A[m_ * SIGDIM + k0_ + kq_]); \
        } \
        _Pragma("unroll") \
        for (int it = 0; it < 4; it++) { \
            int e = tid + it * 128; \
            int kk_ = e >> 5, nq_ = (e & 31) << 2; \
            cp16(&Bs[buf_][kk_][nq_], &Bw[(k0_ + kk_) * U_ + n0 + nq_]); \
        } \
    } while (0)

    BG_ISSUE(0); cp_commit();
    BG_ISSUE(1); cp_commit();
    BG_ISSUE(2); cp_commit();

    for (int t = 0; t < BG_KT; t++) {
        cp_wait<2>();
        __syncthreads();
        int buf = t & 3;
        #pragma unroll
        for (int kk = 0; kk < 16; kk += 2) {
            ulonglong2 q0 = *(const ulonglong2*)&Bs[buf][kk][tx * 8];
            ulonglong2 q1 = *(const ulonglong2*)&Bs[buf][kk][tx * 8 + 4];
            u64 b2a[4] = {q0.x, q0.y, q1.x, q1.y};
            ulonglong2 r0 = *(const ulonglong2*)&Bs[buf][kk + 1][tx * 8];
            ulonglong2 r1 = *(const ulonglong2*)&Bs[buf][kk + 1][tx * 8 + 4];
            u64 b2b[4] = {r0.x, r0.y, r1.x, r1.y};
            #pragma unroll
            for (int i = 0; i < 8; i++) {
                // one LDS64 broadcast covers k and k+1 for this row
                float2 a2 = *(const float2*)&As[buf][ty * 8 + i][kk];
                u64 ap0 = pack2(a2.x);
                u64 ap1 = pack2(a2.y);
                fma2(acc2[i][0], ap0, b2a[0]);
                fma2(acc2[i][1], ap0, b2a[1]);
                fma2(acc2[i][2], ap0, b2a[2]);
                fma2(acc2[i][3], ap0, b2a[3]);
                fma2(acc2[i][0], ap1, b2b[0]);
                fma2(acc2[i][1], ap1, b2b[1]);
                fma2(acc2[i][2], ap1, b2b[2]);
                fma2(acc2[i][3], ap1, b2b[3]);
            }
        }
        if (t + 3 < BG_KT) BG_ISSUE(t + 3);
        cp_commit();
    }

    float* dst = Cpart + ((size_t)(blockIdx.z * NS_BIG + blockIdx.y) * 64 + ty * 8) * U_
               + n0 + tx * 8;
    #pragma unroll
    for (int i = 0; i < 8; i++) {
        *(float4*)&dst[i * U_]     = *(const float4*)&acc2[i][0];
        *(float4*)&dst[i * U_ + 4] = *(const float4*)&acc2[i][2];
    }
#undef BG_ISSUE
}

// ---------------------------------------------------------------------------
// K5: reduce big-GEMM partials (+bias) -> z1, yskip (vectorized)
// ---------------------------------------------------------------------------
__global__ void reduce_big_kernel(const float* __restrict__ b1,
                                  const float* __restrict__ bsk) {
    int idx = blockIdx.x * blockDim.x + threadIdx.x;
    if (idx >= 2 * B_ * U_ / 4) return;
    int z = idx >> 13, r4 = idx & 8191;
    const float4* src = (const float4*)(g_part + (size_t)z * NS_BIG * (B_ * U_)) + r4;
    float4 s = make_float4(0.f, 0.f, 0.f, 0.f);
    #pragma unroll 4
    for (int k = 0; k < NS_BIG; k++) {
        float4 v = src[(size_t)k * (B_ * U_ / 4)];
        s.x += v.x; s.y += v.y; s.z += v.z; s.w += v.w;
    }
    int u = (r4 << 2) & (U_ - 1);
    const float* bb = z ? bsk : b1;
    float4 bv = *(const float4*)&bb[u];
    float* dst = z ? g_yskip : g_z1;
    *(float4*)&dst[r4 << 2] = make_float4(s.x + bv.x, s.y + bv.y, s.z + bv.z, s.w + bv.w);
}

// ---------------------------------------------------------------------------
// K6: generic small GEMM, M=64, N-tile 128, double-buffered, f32x2 inner.
// ---------------------------------------------------------------------------
__global__ void __launch_bounds__(128) gemm64(
    const float* __restrict__ A, int lda, float ascale,
    const float* __restrict__ A2, int lda2, int kHalf,
    int actElu, int K, int kChunk,
    P4 Bset, int ldb, O4 Cset, int ldc)
{
    int z = blockIdx.z;
    const float* __restrict__ Bw = Bset.p[z];
    int n0 = blockIdx.x * 128;
    int kBegin = blockIdx.y * kChunk;
    int kEnd = min(K, kBegin + kChunk);

    __shared__ float As[2][16][68];
    __shared__ float Bs[2][16][128];

    int tid = threadIdx.x;
    int tx = tid & 15, ty = tid >> 4;
    int am = tid >> 2;
    int akq = (tid & 3) << 2;
    int bkk = tid >> 5;
    int bnq = (tid & 31) << 2;

    float4 aR[2], bR[4];

#define GLOAD(K0) do { \
        _Pragma("unroll") \
        for (int it = 0; it < 2; it++) { \
            int m = am + it * 32; \
            int k = (K0) + akq; \
            float4 v = make_float4(0.f, 0.f, 0.f, 0.f); \
            if (k < kEnd) { \
                if (k < kHalf) { \
                    v = *(const float4*)&A[m * lda + k]; \
                    v.x *= ascale; v.y *= ascale; v.z *= ascale; v.w *= ascale; \
                } else { \
                    v = *(const float4*)&A2[m * lda2 + (k - kHalf)]; \
                } \
            } \
            if (actElu) { \
                v.x = (v.x > 0.f) ? v.x : (__expf(v.x) - 1.f); \
                v.y = (v.y > 0.f) ? v.y : (__expf(v.y) - 1.f); \
                v.z = (v.z > 0.f) ? v.z : (__expf(v.z) - 1.f); \
                v.w = (v.w > 0.f) ? v.w : (__expf(v.w) - 1.f); \
            } \
            aR[it] = v; \
        } \
        _Pragma("unroll") \
        for (int it = 0; it < 4; it++) { \
            int k = (K0) + bkk + it * 4; \
            float4 v = make_float4(0.f, 0.f, 0.f, 0.f); \
            if (k < kEnd) v = *(const float4*)&Bw[k * ldb + n0 + bnq]; \
            bR[it] = v; \
        } \
    } while (0)

#define GSTORE(BUF) do { \
        _Pragma("unroll") \
        for (int it = 0; it < 2; it++) { \
            int m = am + it * 32; \
            As[BUF][akq + 0][m] = aR[it].x; As[BUF][akq + 1][m] = aR[it].y; \
            As[BUF][akq + 2][m] = aR[it].z; As[BUF][akq + 3][m] = aR[it].w; \
        } \
        _Pragma("unroll") \
        for (int it = 0; it < 4; it++) { \
            *(float4*)&Bs[BUF][bkk + it * 4][bnq] = bR[it]; \
        } \
    } while (0)

    u64 acc2[8][4];
    #pragma unroll
    for (int i = 0; i < 8; i++)
        #pragma unroll
        for (int j = 0; j < 4; j++) acc2[i][j] = 0ULL;

    GLOAD(kBegin);
    GSTORE(0);
    __syncthreads();

    int buf = 0;
    for (int k0 = kBegin; k0 < kEnd; k0 += 16) {
        bool nxt = (k0 + 16) < kEnd;
        if (nxt) GLOAD(k0 + 16);
        #pragma unroll
        for (int kk = 0; kk < 16; kk++) {
            ulonglong2 q0 = *(const ulonglong2*)&Bs[buf][kk][tx * 8];
            ulonglong2 q1 = *(const ulonglong2*)&Bs[buf][kk][tx * 8 + 4];
            u64 b2[4] = {q0.x, q0.y, q1.x, q1.y};
            float4 alo = *(const float4*)&As[buf][kk][ty * 8];
            float4 ahi = *(const float4*)&As[buf][kk][ty * 8 + 4];
            float a8[8] = {alo.x, alo.y, alo.z, alo.w, ahi.x, ahi.y, ahi.z, ahi.w};
            #pragma unroll
            for (int i = 0; i < 8; i++) {
                u64 ap = pack2(a8[i]);
                fma2(acc2[i][0], ap, b2[0]);
                fma2(acc2[i][1], ap, b2[1]);
                fma2(acc2[i][2], ap, b2[2]);
                fma2(acc2[i][3], ap, b2[3]);
            }
        }
        if (nxt) GSTORE(buf ^ 1);
        __syncthreads();
        buf ^= 1;
    }
    float* C = Cset.p[z];
    #pragma unroll
    for (int i = 0; i < 8; i++) {
        const float* af = (const float*)&acc2[i][0];
        #pragma unroll
        for (int j = 0; j < 8; j++)
            atomicAdd(&C[(ty * 8 + i) * ldc + n0 + tx * 8 + j], af[j]);
    }
#undef GLOAD
#undef GSTORE
}

// ---------------------------------------------------------------------------
// K7: fused glu + layernorm + softmax -> attn
// ---------------------------------------------------------------------------
__global__ void ln_softmax_kernel(const float* __restrict__ gamma,
                                  const float* __restrict__ beta) {
    __shared__ float red[32];
    int b = blockIdx.x, u = threadIdx.x;
    int idx = b * U_ + u;
    float v = g_yskip[idx] + fsigmoid(g_g3[idx]) * g_g4[idx];
    float mu = blockReduceSum(v, red) * (1.0f / (float)U_);
    float d = v - mu;
    float var = blockReduceSum(d * d, red) * (1.0f / (float)U_);
    float yn = d * rsqrtf(var + LN_EPS) * gamma[u] + beta[u];
    float mx = blockReduceMax(yn, red);
    float e = __expf(yn - mx);
    float s = blockReduceSum(e, red);
    g_attn[idx] = e / s;
}

// ---------------------------------------------------------------------------
// K8: P[b,f] = sum_s attn*silu(w), Q[b,f,k] = sum_s attn*bspl_k(w)
// ---------------------------------------------------------------------------
__global__ void __launch_bounds__(128) pq_kernel(const float* __restrict__ x,
                                                 const float* __restrict__ tk) {
    int b = blockIdx.x, chunk = blockIdx.y;
    int f = threadIdx.x;
    int s0 = chunk * 32;

    __shared__ float att_s[32], tk_s[32];
    if (f < 32) {
        att_s[f] = g_attn[b * U_ + s0 + f];
        tk_s[f]  = tk[s0 + f];
    }
    __syncthreads();

    float accP = 0.0f, accQ[8];
    #pragma unroll
    for (int k = 0; k < 8; k++) accQ[k] = 0.0f;

    const float* xb = x + (b * S_ + s0) * F_;
    #pragma unroll 2
    for (int si = 0; si < 32; si++) {
        float att = att_s[si];
        float xw = tk_s[si] * xb[si * F_ + f];
        float th;
        asm("tanh.approx.f32 %0, %1;" : "=f"(th) : "f"(0.5f * xw));
        float sg = fmaf(0.5f, th, 0.5f);
        accP = fmaf(att, xw * sg, accP);
        float c = fmaf(2.5f, xw, 3.5f);
        #pragma unroll
        for (int k = 0; k < 8; k++) {
            float a = fabsf(c - (float)k);
            float a2 = a * a;
            float m = 2.0f - a;
            float p1 = fmaf(fmaf(0.5f, a, -1.0f), a2, 0.66666667f);
            float p2 = m * m * m * (1.0f / 6.0f);
            float v = (a < 1.0f) ? p1 : ((a < 2.0f) ? p2 : 0.0f);
            accQ[k] = fmaf(att, v, accQ[k]);
        }
    }
    atomicAdd(&g_PQ[b * 1152 + f], accP);
    #pragma unroll
    for (int k = 0; k < 8; k++)
        atomicAdd(&g_PQ[b * 1152 + 128 + f * 8 + k], accQ[k]);
}

// ---------------------------------------------------------------------------
// K9: LSTM elementwise -> out = [h_new | c_new]
// ---------------------------------------------------------------------------
__global__ void final_kernel(const float* __restrict__ c_prev, float* __restrict__ out) {
    int idx = blockIdx.x * blockDim.x + threadIdx.x;
    if (idx >= B_ * U_) return;
    float f = fsigmoid(g_gates[idx]);
    float i = fsigmoid(g_gates[32768 + idx]);
    float cand = tanhf(g_gates[65536 + idx]);
    float o = fsigmoid(g_gates[98304 + idx]);
    float c = f * c_prev[idx] + i * cand;
    float h = o * tanhf(c);
    out[idx] = h;
    out[B_ * U_ + idx] = c;
}

// ---------------------------------------------------------------------------
// Host launcher
// ---------------------------------------------------------------------------
extern "C" void kernel_launch(void* const* d_in, const int* in_sizes, int n_in,
                              void* d_out, int out_size) {
    const float* x        = (const float*)d_in[0];
    const float* h_prev   = (const float*)d_in[1];
    const float* c_prev   = (const float*)d_in[2];
    const float* tk       = (const float*)d_in[3];
    const float* base_w   = (const float*)d_in[4];
    const float* spline_w = (const float*)d_in[5];
    const float* w1       = (const float*)d_in[6];
    const float* b1       = (const float*)d_in[7];
    const float* w2       = (const float*)d_in[8];
    const float* b2       = (const float*)d_in[9];
    const float* w3       = (const float*)d_in[10];
    const float* b3       = (const float*)d_in[11];
    const float* w4       = (const float*)d_in[12];
    const float* b4       = (const float*)d_in[13];
    const float* ws       = (const float*)d_in[14];
    const float* bsk      = (const float*)d_in[15];
    const float* gamma    = (const float*)d_in[16];
    const float* beta     = (const float*)d_in[17];
    const float* wf       = (const float*)d_in[18];
    const float* bf       = (const float*)d_in[19];
    const float* wi       = (const float*)d_in[20];
    const float* bi       = (const float*)d_in[21];
    const float* wc       = (const float*)d_in[22];
    const float* bc       = (const float*)d_in[23];
    const float* wo       = (const float*)d_in[24];
    const float* bo       = (const float*)d_in[25];
    float* out = (float*)d_out;

    float *p_sig, *p_z1, *p_h2, *p_g3, *p_g4, *p_PQ, *p_Wc, *p_cur, *p_gates, *p_part;
    cudaGetSymbolAddress((void**)&p_sig,   g_sig);
    cudaGetSymbolAddress((void**)&p_z1,    g_z1);
    cudaGetSymbolAddress((void**)&p_h2,    g_h2);
    cudaGetSymbolAddress((void**)&p_g3,    g_g3);
    cudaGetSymbolAddress((void**)&p_g4,    g_g4);
    cudaGetSymbolAddress((void**)&p_PQ,    g_PQ);
    cudaGetSymbolAddress((void**)&p_Wc,    g_Wc);
    cudaGetSymbolAddress((void**)&p_cur,   g_cur);
    cudaGetSymbolAddress((void**)&p_gates, g_gates);
    cudaGetSymbolAddress((void**)&p_part,  g_part);

    // (1) fused init: biases/zeros/base_w->Wc/s1 + spline transpose
    init_fused_kernel<<<INIT_BLOCKS + 512, 256>>>(b2, b3, b4, bf, bi, bc, bo,
                                                  base_w, spline_w, x, tk);
    // (2) signature level-2 (8 splits, cp.async, f32x2)
    sig2_kernel<<<dim3(8, B_), 256>>>(x, tk);
    // (3) signature epilogue
    sig_epi_kernel<<<dim3(4, 4, B_), 256>>>(x, tk);
    // (4) BIG fused sig projections (pair-k A broadcasts) -> partials
    bgemm<<<dim3(4, NS_BIG, 2), 128>>>(p_sig, w1, ws, p_part);
    // (5) reduce partials + bias -> z1, yskip
    reduce_big_kernel<<<(2 * B_ * U_ / 4 + 255) / 256, 256>>>(b1, bsk);
    // (6) GRN: h2 = elu(z1)@w2 + b2
    {
        P4 Bb; Bb.p[0] = w2; Bb.p[1] = w2; Bb.p[2] = w2; Bb.p[3] = w2;
        O4 Cb; Cb.p[0] = p_h2; Cb.p[1] = p_h2; Cb.p[2] = p_h2; Cb.p[3] = p_h2;
        gemm64<<<dim3(4, 8, 1), 128>>>(p_z1, U_, 1.0f, p_z1, U_, U_,
                                       1, U_, 64, Bb, U_, Cb, U_);
    }
    // (7) g3, g4 fused
    {
        P4 Bb; Bb.p[0] = w3; Bb.p[1] = w4; Bb.p[2] = w3; Bb.p[3] = w3;
        O4 Cb; Cb.p[0] = p_g3; Cb.p[1] = p_g4; Cb.p[2] = p_g3; Cb.p[3] = p_g3;
        gemm64<<<dim3(4, 8, 2), 128>>>(p_h2, U_, 1.0f, p_h2, U_, U_,
                                       0, U_, 64, Bb, U_, Cb, U_);
    }
    // (8) glu + LN + softmax
    ln_softmax_kernel<<<B_, U_>>>(gamma, beta);
    // (9) attention-weighted KAN reductions
    pq_kernel<<<dim3(B_, 16), 128>>>(x, tk);
    // (10) current = PQ @ Wc
    {
        P4 Bb; Bb.p[0] = p_Wc; Bb.p[1] = p_Wc; Bb.p[2] = p_Wc; Bb.p[3] = p_Wc;
        O4 Cb; Cb.p[0] = p_cur; Cb.p[1] = p_cur; Cb.p[2] = p_cur; Cb.p[3] = p_cur;
        gemm64<<<dim3(4, 8, 1), 128>>>(p_PQ, 1152, 1.0f, p_PQ, 1152, 1152,
                                       0, 1152, 144, Bb, U_, Cb, U_);
    }
    // (11) LSTM gates: A = [cur/S , h_prev]; 4 gates fused
    {
        P4 Bb; Bb.p[0] = wf; Bb.p[1] = wi; Bb.p[2] = wc; Bb.p[3] = wo;
        O4 Cb; Cb.p[0] = p_gates; Cb.p[1] = p_gates + 32768;
        Cb.p[2] = p_gates + 65536; Cb.p[3] = p_gates + 98304;
        gemm64<<<dim3(4, 8, 4), 128>>>(p_cur, U_, 1.0f / (float)S_, h_prev, U_, U_,
                                       0, 2 * U_, 128, Bb, U_, Cb, U_);
    }
    // (12) LSTM elementwise
    final_kernel<<<(B_ * U_ + 255) / 256, 256>>>(c_prev, out);
}

// round 17
// speedup vs baseline: 1.4118x; 1.0023x over previous
#include <cuda_runtime.h>
#include <math.h>
#include <stdint.h>

// ---------------------------------------------------------------------------
// Problem constants
// ---------------------------------------------------------------------------
#define B_   64
#define S_   512
#define F_   128
#define U_   512
#define SIGDIM 16512            // F + F*F
#define NB_  8
#define LN_EPS 1e-3f
#define NS_BIG 129              // splits for big GEMM: 129 * 128 = 16512
#define BG_KT  8                // k-tiles (of 16) per split: 8*16 = 128

typedef unsigned long long u64;

// ---------------------------------------------------------------------------
// Device scratch
// ---------------------------------------------------------------------------
__device__ float g_sig  [B_ * SIGDIM];
__device__ float g_M    [B_ * F_ * F_];
__device__ float g_part [2 * NS_BIG * B_ * U_];   // 33.8 MB split partials
__device__ float g_z1   [B_ * U_];
__device__ float g_yskip[B_ * U_];
__device__ float g_h2   [B_ * U_];
__device__ float g_g3   [B_ * U_];
__device__ float g_g4   [B_ * U_];
__device__ float g_attn [B_ * U_];
__device__ float g_PQ   [B_ * 1152];
__device__ float g_Wc   [1152 * U_];
__device__ float g_cur  [B_ * U_];
__device__ float g_gates[4 * B_ * U_];

struct P4 { const float* p[4]; };
struct O4 { float* p[4]; };

// ---------------------------------------------------------------------------
// Helpers
// ---------------------------------------------------------------------------
__device__ __forceinline__ float fsigmoid(float x) { return 1.0f / (1.0f + __expf(-x)); }

__device__ __forceinline__ void cp16(void* s, const void* g) {
    uint32_t a = (uint32_t)__cvta_generic_to_shared(s);
    asm volatile("cp.async.cg.shared.global [%0], [%1], 16;" :: "r"(a), "l"(g));
}
__device__ __forceinline__ void cp_commit() { asm volatile("cp.async.commit_group;"); }
template<int N> __device__ __forceinline__ void cp_wait() {
    asm volatile("cp.async.wait_group %0;" :: "n"(N));
}

// packed f32x2 helpers (Blackwell): 2 fp32 FMAs per issue slot
__device__ __forceinline__ u64 pack2(float a) {
    u64 r; asm("mov.b64 %0, {%1, %1};" : "=l"(r) : "f"(a)); return r;
}
__device__ __forceinline__ void fma2(u64& d, u64 a, u64 b) {
    asm("fma.rn.f32x2 %0, %1, %2, %0;" : "+l"(d) : "l"(a), "l"(b));
}

__device__ __forceinline__ float blockReduceSum(float v, float* smem) {
    int lane = threadIdx.x & 31, w = threadIdx.x >> 5;
    #pragma unroll
    for (int o = 16; o > 0; o >>= 1) v += __shfl_xor_sync(0xffffffffu, v, o);
    if (lane == 0) smem[w] = v;
    __syncthreads();
    int nw = blockDim.x >> 5;
    float r = (threadIdx.x < nw) ? smem[threadIdx.x] : 0.0f;
    if (w == 0) {
        #pragma unroll
        for (int o = 16; o > 0; o >>= 1) r += __shfl_xor_sync(0xffffffffu, r, o);
        if (lane == 0) smem[0] = r;
    }
    __syncthreads();
    float out = smem[0];
    __syncthreads();
    return out;
}

__device__ __forceinline__ float blockReduceMax(float v, float* smem) {
    int lane = threadIdx.x & 31, w = threadIdx.x >> 5;
    #pragma unroll
    for (int o = 16; o > 0; o >>= 1) v = fmaxf(v, __shfl_xor_sync(0xffffffffu, v, o));
    if (lane == 0) smem[w] = v;
    __syncthreads();
    int nw = blockDim.x >> 5;
    float r = (threadIdx.x < nw) ? smem[threadIdx.x] : -INFINITY;
    if (w == 0) {
        #pragma unroll
        for (int o = 16; o > 0; o >>= 1) r = fmaxf(r, __shfl_xor_sync(0xffffffffu, r, o));
        if (lane == 0) smem[0] = r;
    }
    __syncthreads();
    float out = smem[0];
    __syncthreads();
    return out;
}

// ---------------------------------------------------------------------------
// K1: fused init: biases (h2,g3,g4,gates), zeros (cur/PQ/M), base_w->Wc, s1,
//     PLUS spline_w transpose tiles (blocks >= INIT_BLOCKS).
// ---------------------------------------------------------------------------
#define NBIAS_  (7 * B_ * U_)
#define NINIT_  (NBIAS_ + B_*U_ + B_*1152 + B_*F_*F_ + F_*U_ + B_*F_)
#define INIT_BLOCKS ((NINIT_ + 255) / 256)

__global__ void __launch_bounds__(256) init_fused_kernel(
        const float* b2, const float* b3, const float* b4,
        const float* bf, const float* bi, const float* bc, const float* bo,
        const float* base_w, const float* __restrict__ spline_w,
        const float* __restrict__ x, const float* __restrict__ tk) {
    if (blockIdx.x >= INIT_BLOCKS) {
        // spline transpose tile: Wc[128+kk][u] = spline_w[u][kk]
        __shared__ float tile[32][33];
        int bid = blockIdx.x - INIT_BLOCKS;          // 0..511
        int kk0 = (bid & 31) * 32, u0 = (bid >> 5) * 32;
        int tx = threadIdx.x & 31, ty = threadIdx.x >> 5;
        #pragma unroll
        for (int a = 0; a < 32; a += 8)
            tile[ty + a][tx] = spline_w[(u0 + ty + a) * 1024 + kk0 + tx];
        __syncthreads();
        #pragma unroll
        for (int a = 0; a < 32; a += 8)
            g_Wc[(F_ + kk0 + ty + a) * U_ + u0 + tx] = tile[tx][ty + a];
        return;
    }
    int idx = blockIdx.x * blockDim.x + threadIdx.x;
    if (idx < NBIAS_) {
        int which = idx >> 15;
        int r = idx & 32767;
        int u = r & (U_ - 1);
        float v; float* dst;
        switch (which) {
            case 0: dst = g_h2;            v = b2[u];  break;
            case 1: dst = g_g3;            v = b3[u];  break;
            case 2: dst = g_g4;            v = b4[u];  break;
            case 3: dst = g_gates;         v = bf[u];  break;
            case 4: dst = g_gates + 32768; v = bi[u];  break;
            case 5: dst = g_gates + 65536; v = bc[u];  break;
            default: dst = g_gates + 98304; v = bo[u]; break;
        }
        dst[r] = v;
        return;
    }
    int r = idx - NBIAS_;
    if (r < B_ * U_) { g_cur[r] = 0.0f; return; }
    r -= B_ * U_;
    if (r < B_ * 1152) { g_PQ[r] = 0.0f; return; }
    r -= B_ * 1152;
    if (r < B_ * F_ * F_) { g_M[r] = 0.0f; return; }
    r -= B_ * F_ * F_;
    if (r < F_ * U_) { g_Wc[r] = base_w[r]; return; }
    r -= F_ * U_;
    if (r < B_ * F_) {
        int b = r >> 7, c = r & 127;
        g_sig[b * SIGDIM + c] = tk[S_ - 1] * x[(b * S_ + S_ - 1) * F_ + c]
                              - tk[0]      * x[b * S_ * F_ + c];
    }
}

// ---------------------------------------------------------------------------
// K2: M[b,i,j] = sum_t (tk_t*tk_{t+1}) x_t[i] x_{t+1}[j]
// 8 splits of 64 products; cp.async double-buffered; f32x2 inner loop.
// ---------------------------------------------------------------------------
__global__ void __launch_bounds__(256) sig2_kernel(const float* __restrict__ x,
                                                   const float* __restrict__ tk) {
    int b = blockIdx.y;
    int tBegin = blockIdx.x * 64;
    __shared__ float Xs[2][33][128];
    __shared__ float sprod[64];

    int tid = threadIdx.x;

    if (tid < 64) {
        int t = tBegin + tid;
        sprod[tid] = (t < S_ - 1) ? tk[t] * tk[t + 1] : 0.0f;
    }

#define S2_ISSUE(SS) do { \
        int rowBase = (SS) * 32; int buf_ = (SS) & 1; \
        _Pragma("unroll") \
        for (int it = 0; it < 5; it++) { \
            int e = tid + it * 256; \
            if (e < 33 * 32) { \
                int r = e >> 5, c4 = (e & 31) << 2; \
                int gr = tBegin + rowBase + r; \
                if (gr > S_ - 1) gr = S_ - 1; \
                cp16(&Xs[buf_][r][c4], &x[((size_t)b * S_ + gr) * F_ + c4]); \
            } \
        } \
    } while (0)

#define S2_COMPUTE(TT) do { \
        int buf_ = (TT) & 1; int kb = (TT) * 32; \
        _Pragma("unroll") \
        for (int kk = 0; kk < 32; kk++) { \
            float s_ = sprod[kb + kk]; \
            ulonglong2 q0 = *(const ulonglong2*)&Xs[buf_][kk + 1][tx * 8]; \
            ulonglong2 q1 = *(const ulonglong2*)&Xs[buf_][kk + 1][tx * 8 + 4]; \
            u64 d2[4] = {q0.x, q0.y, q1.x, q1.y}; \
            float4 alo = *(const float4*)&Xs[buf_][kk][ty * 8]; \
            float4 ahi = *(const float4*)&Xs[buf_][kk][ty * 8 + 4]; \
            float a8[8] = {alo.x * s_, alo.y * s_, alo.z * s_, alo.w * s_, \
                           ahi.x * s_, ahi.y * s_, ahi.z * s_, ahi.w * s_}; \
            _Pragma("unroll") \
            for (int i = 0; i < 8; i++) { \
                u64 ap = pack2(a8[i]); \
                fma2(acc2[i][0], ap, d2[0]); \
                fma2(acc2[i][1], ap, d2[1]); \
                fma2(acc2[i][2], ap, d2[2]); \
                fma2(acc2[i][3], ap, d2[3]); \
            } \
        } \
    } while (0)

    S2_ISSUE(0); cp_commit();
    S2_ISSUE(1); cp_commit();

    int tx = tid & 15, ty = tid >> 4;
    u64 acc2[8][4];
    #pragma unroll
    for (int i = 0; i < 8; i++)
        #pragma unroll
        for (int j = 0; j < 4; j++) acc2[i][j] = 0ULL;

    cp_wait<1>(); __syncthreads();
    S2_COMPUTE(0);
    cp_wait<0>(); __syncthreads();
    S2_COMPUTE(1);

    float* Mb = g_M + b * F_ * F_;
    #pragma unroll
    for (int i = 0; i < 8; i++) {
        const float* af = (const float*)&acc2[i][0];
        #pragma unroll
        for (int j = 0; j < 8; j++)
            atomicAdd(&Mb[(ty * 8 + i) * F_ + tx * 8 + j], af[j]);
    }
#undef S2_ISSUE
#undef S2_COMPUTE
}

// ---------------------------------------------------------------------------
// K3: sig epilogue (tiled): s2 = 0.5(M - M^T) + 0.5 wL(x)wL + 0.5 w0(x)w0 - w0(x)wL
// ---------------------------------------------------------------------------
__global__ void __launch_bounds__(256) sig_epi_kernel(const float* __restrict__ x,
                                                      const float* __restrict__ tk) {
    int b = blockIdx.z;
    int i0 = blockIdx.y * 32, j0 = blockIdx.x * 32;
    __shared__ float tji[32][33];
    __shared__ float w0i_s[32], wLi_s[32], w0j_s[32], wLj_s[32];

    int tx = threadIdx.x & 31, ty = threadIdx.x >> 5;
    const float* Mb = g_M + b * F_ * F_;
    #pragma unroll
    for (int a = 0; a < 32; a += 8)
        tji[ty + a][tx] = Mb[(j0 + ty + a) * F_ + i0 + tx];
    if (threadIdx.x < 32) {
        float tk0 = tk[0], tkL = tk[S_ - 1];
        const float* xb = x + b * S_ * F_;
        w0i_s[tx] = tk0 * xb[i0 + tx];
        wLi_s[tx] = tkL * xb[(S_ - 1) * F_ + i0 + tx];
        w0j_s[tx] = tk0 * xb[j0 + tx];
        wLj_s[tx] = tkL * xb[(S_ - 1) * F_ + j0 + tx];
    }
    __syncthreads();

    float* dst = g_sig + b * SIGDIM + F_;
    float w0j = w0j_s[tx], wLj = wLj_s[tx];
    #pragma unroll
    for (int a = 0; a < 32; a += 8) {
        int i = i0 + ty + a, j = j0 + tx;
        float mij = Mb[i * F_ + j];
        float mji = tji[tx][ty + a];
        float w0i = w0i_s[ty + a], wLi = wLi_s[ty + a];
        dst[i * F_ + j] = 0.5f * (mij - mji)
                        + 0.5f * wLi * wLj + 0.5f * w0i * w0j - w0i * wLj;
    }
}

// ---------------------------------------------------------------------------
// K4: BIG GEMM, cp.async 4-stage, f32x2 inner (round-13 body).
// grid (4, 129, 2). 128 threads, 64x128 tile, 8x8/thread, zero atomics.
// ---------------------------------------------------------------------------
__global__ void __launch_bounds__(128) bgemm(const float* __restrict__ A,
                                             const float* __restrict__ Bw0,
                                             const float* __restrict__ Bw1,
                                             float* __restrict__ Cpart) {
    const float* __restrict__ Bw = blockIdx.z ? Bw1 : Bw0;
    int n0 = blockIdx.x * 128;
    int kBegin = blockIdx.y * (BG_KT * 16);

    __shared__ float As[4][64][16];        // [stage][m][kk]
    __shared__ float Bs[4][16][128];       // [stage][kk][n]

    int tid = threadIdx.x;
    int ty = tid >> 4, tx = tid & 15;      // rows ty*8.., cols tx*8..

    u64 acc2[8][4];
    #pragma unroll
    for (int i = 0; i < 8; i++)
        #pragma unroll
        for (int j = 0; j < 4; j++) acc2[i][j] = 0ULL;

#define BG_ISSUE(T) do { \
        int k0_ = kBegin + (T) * 16; int buf_ = (T) & 3; \
        _Pragma("unroll") \
        for (int it = 0; it < 2; it++) { \
            int e = tid + it * 128; \
            int m_ = e >> 2, kq_ = (e & 3) << 2; \
            cp16(&As[buf_][m_][kq_], &A[m_ * SIGDIM + k0_ + kq_]); \
        } \
        _Pragma("unroll") \
        for (int it = 0; it < 4; it++) { \
            int e = tid + it * 128; \
            int kk_ = e >> 5, nq_ = (e & 31) << 2; \
            cp16(&Bs[buf_][kk_][nq_], &Bw[(k0_ + kk_) * U_ + n0 + nq_]); \
        } \
    } while (0)

    BG_ISSUE(0); cp_commit();
    BG_ISSUE(1); cp_commit();
    BG_ISSUE(2); cp_commit();

    for (int t = 0; t < BG_KT; t++) {
        cp_wait<2>();
        __syncthreads();
        int buf = t & 3;
        #pragma unroll
        for (int kk = 0; kk < 16; kk++) {
            ulonglong2 q0 = *(const ulonglong2*)&Bs[buf][kk][tx * 8];
            ulonglong2 q1 = *(const ulonglong2*)&Bs[buf][kk][tx * 8 + 4];
            u64 b2[4] = {q0.x, q0.y, q1.x, q1.y};
            #pragma unroll
            for (int i = 0; i < 8; i++) {
                u64 ap = pack2(As[buf][ty * 8 + i][kk]);
                fma2(acc2[i][0], ap, b2[0]);
                fma2(acc2[i][1], ap, b2[1]);
                fma2(acc2[i][2], ap, b2[2]);
                fma2(acc2[i][3], ap, b2[3]);
            }
        }
        if (t + 3 < BG_KT) BG_ISSUE(t + 3);
        cp_commit();
    }

    float* dst = Cpart + ((size_t)(blockIdx.z * NS_BIG + blockIdx.y) * 64 + ty * 8) * U_
               + n0 + tx * 8;
    #pragma unroll
    for (int i = 0; i < 8; i++) {
        *(float4*)&dst[i * U_]     = *(const float4*)&acc2[i][0];
        *(float4*)&dst[i * U_ + 4] = *(const float4*)&acc2[i][2];
    }
#undef BG_ISSUE
}

// ---------------------------------------------------------------------------
// K5: reduce big-GEMM partials (+bias) -> z1, yskip (vectorized)
// ---------------------------------------------------------------------------
__global__ void reduce_big_kernel(const float* __restrict__ b1,
                                  const float* __restrict__ bsk) {
    int idx = blockIdx.x * blockDim.x + threadIdx.x;
    if (idx >= 2 * B_ * U_ / 4) return;
    int z = idx >> 13, r4 = idx & 8191;
    const float4* src = (const float4*)(g_part + (size_t)z * NS_BIG * (B_ * U_)) + r4;
    float4 s = make_float4(0.f, 0.f, 0.f, 0.f);
    #pragma unroll 4
    for (int k = 0; k < NS_BIG; k++) {
        float4 v = src[(size_t)k * (B_ * U_ / 4)];
        s.x += v.x; s.y += v.y; s.z += v.z; s.w += v.w;
    }
    int u = (r4 << 2) & (U_ - 1);
    const float* bb = z ? bsk : b1;
    float4 bv = *(const float4*)&bb[u];
    float* dst = z ? g_yskip : g_z1;
    *(float4*)&dst[r4 << 2] = make_float4(s.x + bv.x, s.y + bv.y, s.z + bv.z, s.w + bv.w);
}

// ---------------------------------------------------------------------------
// K6: generic small GEMM, M=64, N-tile 128, double-buffered, f32x2 inner.
// ---------------------------------------------------------------------------
__global__ void __launch_bounds__(128) gemm64(
    const float* __restrict__ A, int lda, float ascale,
    const float* __restrict__ A2, int lda2, int kHalf,
    int actElu, int K, int kChunk,
    P4 Bset, int ldb, O4 Cset, int ldc)
{
    int z = blockIdx.z;
    const float* __restrict__ Bw = Bset.p[z];
    int n0 = blockIdx.x * 128;
    int kBegin = blockIdx.y * kChunk;
    int kEnd = min(K, kBegin + kChunk);

    __shared__ float As[2][16][68];
    __shared__ float Bs[2][16][128];

    int tid = threadIdx.x;
    int tx = tid & 15, ty = tid >> 4;
    int am = tid >> 2;
    int akq = (tid & 3) << 2;
    int bkk = tid >> 5;
    int bnq = (tid & 31) << 2;

    float4 aR[2], bR[4];

#define GLOAD(K0) do { \
        _Pragma("unroll") \
        for (int it = 0; it < 2; it++) { \
            int m = am + it * 32; \
            int k = (K0) + akq; \
            float4 v = make_float4(0.f, 0.f, 0.f, 0.f); \
            if (k < kEnd) { \
                if (k < kHalf) { \
                    v = *(const float4*)&A[m * lda + k]; \
                    v.x *= ascale; v.y *= ascale; v.z *= ascale; v.w *= ascale; \
                } else { \
                    v = *(const float4*)&A2[m * lda2 + (k - kHalf)]; \
                } \
            } \
            if (actElu) { \
                v.x = (v.x > 0.f) ? v.x : (__expf(v.x) - 1.f); \
                v.y = (v.y > 0.f) ? v.y : (__expf(v.y) - 1.f); \
                v.z = (v.z > 0.f) ? v.z : (__expf(v.z) - 1.f); \
                v.w = (v.w > 0.f) ? v.w : (__expf(v.w) - 1.f); \
            } \
            aR[it] = v; \
        } \
        _Pragma("unroll") \
        for (int it = 0; it < 4; it++) { \
            int k = (K0) + bkk + it * 4; \
            float4 v = make_float4(0.f, 0.f, 0.f, 0.f); \
            if (k < kEnd) v = *(const float4*)&Bw[k * ldb + n0 + bnq]; \
            bR[it] = v; \
        } \
    } while (0)

#define GSTORE(BUF) do { \
        _Pragma("unroll") \
        for (int it = 0; it < 2; it++) { \
            int m = am + it * 32; \
            As[BUF][akq + 0][m] = aR[it].x; As[BUF][akq + 1][m] = aR[it].y; \
            As[BUF][akq + 2][m] = aR[it].z; As[BUF][akq + 3][m] = aR[it].w; \
        } \
        _Pragma("unroll") \
        for (int it = 0; it < 4; it++) { \
            *(float4*)&Bs[BUF][bkk + it * 4][bnq] = bR[it]; \
        } \
    } while (0)

    u64 acc2[8][4];
    #pragma unroll
    for (int i = 0; i < 8; i++)
        #pragma unroll
        for (int j = 0; j < 4; j++) acc2[i][j] = 0ULL;

    GLOAD(kBegin);
    GSTORE(0);
    __syncthreads();

    int buf = 0;
    for (int k0 = kBegin; k0 < kEnd; k0 += 16) {
        bool nxt = (k0 + 16) < kEnd;
        if (nxt) GLOAD(k0 + 16);
        #pragma unroll
        for (int kk = 0; kk < 16; kk++) {
            ulonglong2 q0 = *(const ulonglong2*)&Bs[buf][kk][tx * 8];
            ulonglong2 q1 = *(const ulonglong2*)&Bs[buf][kk][tx * 8 + 4];
            u64 b2[4] = {q0.x, q0.y, q1.x, q1.y};
            float4 alo = *(const float4*)&As[buf][kk][ty * 8];
            float4 ahi = *(const float4*)&As[buf][kk][ty * 8 + 4];
            float a8[8] = {alo.x, alo.y, alo.z, alo.w, ahi.x, ahi.y, ahi.z, ahi.w};
            #pragma unroll
            for (int i = 0; i < 8; i++) {
                u64 ap = pack2(a8[i]);
                fma2(acc2[i][0], ap, b2[0]);
                fma2(acc2[i][1], ap, b2[1]);
                fma2(acc2[i][2], ap, b2[2]);
                fma2(acc2[i][3], ap, b2[3]);
            }
        }
        if (nxt) GSTORE(buf ^ 1);
        __syncthreads();
        buf ^= 1;
    }
    float* C = Cset.p[z];
    #pragma unroll
    for (int i = 0; i < 8; i++) {
        const float* af = (const float*)&acc2[i][0];
        #pragma unroll
        for (int j = 0; j < 8; j++)
            atomicAdd(&C[(ty * 8 + i) * ldc + n0 + tx * 8 + j], af[j]);
    }
#undef GLOAD
#undef GSTORE
}

// ---------------------------------------------------------------------------
// K7: fused glu + layernorm + softmax -> attn
// ---------------------------------------------------------------------------
__global__ void ln_softmax_kernel(const float* __restrict__ gamma,
                                  const float* __restrict__ beta) {
    __shared__ float red[32];
    int b = blockIdx.x, u = threadIdx.x;
    int idx = b * U_ + u;
    float v = g_yskip[idx] + fsigmoid(g_g3[idx]) * g_g4[idx];
    float mu = blockReduceSum(v, red) * (1.0f / (float)U_);
    float d = v - mu;
    float var = blockReduceSum(d * d, red) * (1.0f / (float)U_);
    float yn = d * rsqrtf(var + LN_EPS) * gamma[u] + beta[u];
    float mx = blockReduceMax(yn, red);
    float e = __expf(yn - mx);
    float s = blockReduceSum(e, red);
    g_attn[idx] = e / s;
}

// ---------------------------------------------------------------------------
// K8: P[b,f] = sum_s attn*silu(w), Q[b,f,k] = sum_s attn*bspl_k(w)
// ---------------------------------------------------------------------------
__global__ void __launch_bounds__(128) pq_kernel(const float* __restrict__ x,
                                                 const float* __restrict__ tk) {
    int b = blockIdx.x, chunk = blockIdx.y;
    int f = threadIdx.x;
    int s0 = chunk * 32;

    __shared__ float att_s[32], tk_s[32];
    if (f < 32) {
        att_s[f] = g_attn[b * U_ + s0 + f];
        tk_s[f]  = tk[s0 + f];
    }
    __syncthreads();

    float accP = 0.0f, accQ[8];
    #pragma unroll
    for (int k = 0; k < 8; k++) accQ[k] = 0.0f;

    const float* xb = x + (b * S_ + s0) * F_;
    #pragma unroll 2
    for (int si = 0; si < 32; si++) {
        float att = att_s[si];
        float xw = tk_s[si] * xb[si * F_ + f];
        float th;
        asm("tanh.approx.f32 %0, %1;" : "=f"(th) : "f"(0.5f * xw));
        float sg = fmaf(0.5f, th, 0.5f);
        accP = fmaf(att, xw * sg, accP);
        float c = fmaf(2.5f, xw, 3.5f);
        #pragma unroll
        for (int k = 0; k < 8; k++) {
            float a = fabsf(c - (float)k);
            float a2 = a * a;
            float m = 2.0f - a;
            float p1 = fmaf(fmaf(0.5f, a, -1.0f), a2, 0.66666667f);
            float p2 = m * m * m * (1.0f / 6.0f);
            float v = (a < 1.0f) ? p1 : ((a < 2.0f) ? p2 : 0.0f);
            accQ[k] = fmaf(att, v, accQ[k]);
        }
    }
    atomicAdd(&g_PQ[b * 1152 + f], accP);
    #pragma unroll
    for (int k = 0; k < 8; k++)
        atomicAdd(&g_PQ[b * 1152 + 128 + f * 8 + k], accQ[k]);
}

// ---------------------------------------------------------------------------
// K9: LSTM elementwise -> out = [h_new | c_new]
// ---------------------------------------------------------------------------
__global__ void final_kernel(const float* __restrict__ c_prev, float* __restrict__ out) {
    int idx = blockIdx.x * blockDim.x + threadIdx.x;
    if (idx >= B_ * U_) return;
    float f = fsigmoid(g_gates[idx]);
    float i = fsigmoid(g_gates[32768 + idx]);
    float cand = tanhf(g_gates[65536 + idx]);
    float o = fsigmoid(g_gates[98304 + idx]);
    float c = f * c_prev[idx] + i * cand;
    float h = o * tanhf(c);
    out[idx] = h;
    out[B_ * U_ + idx] = c;
}

// ---------------------------------------------------------------------------
// Host launcher
// ---------------------------------------------------------------------------
extern "C" void kernel_launch(void* const* d_in, const int* in_sizes, int n_in,
                              void* d_out, int out_size) {
    const float* x        = (const float*)d_in[0];
    const float* h_prev   = (const float*)d_in[1];
    const float* c_prev   = (const float*)d_in[2];
    const float* tk       = (const float*)d_in[3];
    const float* base_w   = (const float*)d_in[4];
    const float* spline_w = (const float*)d_in[5];
    const float* w1       = (const float*)d_in[6];
    const float* b1       = (const float*)d_in[7];
    const float* w2       = (const float*)d_in[8];
    const float* b2       = (const float*)d_in[9];
    const float* w3       = (const float*)d_in[10];
    const float* b3       = (const float*)d_in[11];
    const float* w4       = (const float*)d_in[12];
    const float* b4       = (const float*)d_in[13];
    const float* ws       = (const float*)d_in[14];
    const float* bsk      = (const float*)d_in[15];
    const float* gamma    = (const float*)d_in[16];
    const float* beta     = (const float*)d_in[17];
    const float* wf       = (const float*)d_in[18];
    const float* bf       = (const float*)d_in[19];
    const float* wi       = (const float*)d_in[20];
    const float* bi       = (const float*)d_in[21];
    const float* wc       = (const float*)d_in[22];
    const float* bc       = (const float*)d_in[23];
    const float* wo       = (const float*)d_in[24];
    const float* bo       = (const float*)d_in[25];
    float* out = (float*)d_out;

    float *p_sig, *p_z1, *p_h2, *p_g3, *p_g4, *p_PQ, *p_Wc, *p_cur, *p_gates, *p_part;
    cudaGetSymbolAddress((void**)&p_sig,   g_sig);
    cudaGetSymbolAddress((void**)&p_z1,    g_z1);
    cudaGetSymbolAddress((void**)&p_h2,    g_h2);
    cudaGetSymbolAddress((void**)&p_g3,    g_g3);
    cudaGetSymbolAddress((void**)&p_g4,    g_g4);
    cudaGetSymbolAddress((void**)&p_PQ,    g_PQ);
    cudaGetSymbolAddress((void**)&p_Wc,    g_Wc);
    cudaGetSymbolAddress((void**)&p_cur,   g_cur);
    cudaGetSymbolAddress((void**)&p_gates, g_gates);
    cudaGetSymbolAddress((void**)&p_part,  g_part);

    // (1) fused init: biases/zeros/base_w->Wc/s1 + spline transpose
    init_fused_kernel<<<INIT_BLOCKS + 512, 256>>>(b2, b3, b4, bf, bi, bc, bo,
                                                  base_w, spline_w, x, tk);
    // (2) signature level-2 (8 splits, cp.async, f32x2)
    sig2_kernel<<<dim3(8, B_), 256>>>(x, tk);
    // (3) signature epilogue
    sig_epi_kernel<<<dim3(4, 4, B_), 256>>>(x, tk);
    // (4) BIG fused sig projections (129 splits of 128) -> partials
    bgemm<<<dim3(4, NS_BIG, 2), 128>>>(p_sig, w1, ws, p_part);
    // (5) reduce partials + bias -> z1, yskip
    reduce_big_kernel<<<(2 * B_ * U_ / 4 + 255) / 256, 256>>>(b1, bsk);
    // (6) GRN: h2 = elu(z1)@w2 + b2   (16 splits)
    {
        P4 Bb; Bb.p[0] = w2; Bb.p[1] = w2; Bb.p[2] = w2; Bb.p[3] = w2;
        O4 Cb; Cb.p[0] = p_h2; Cb.p[1] = p_h2; Cb.p[2] = p_h2; Cb.p[3] = p_h2;
        gemm64<<<dim3(4, 16, 1), 128>>>(p_z1, U_, 1.0f, p_z1, U_, U_,
                                        1, U_, 32, Bb, U_, Cb, U_);
    }
    // (7) g3, g4 fused (16 splits)
    {
        P4 Bb; Bb.p[0] = w3; Bb.p[1] = w4; Bb.p[2] = w3; Bb.p[3] = w3;
        O4 Cb; Cb.p[0] = p_g3; Cb.p[1] = p_g4; Cb.p[2] = p_g3; Cb.p[3] = p_g3;
        gemm64<<<dim3(4, 16, 2), 128>>>(p_h2, U_, 1.0f, p_h2, U_, U_,
                                        0, U_, 32, Bb, U_, Cb, U_);
    }
    // (8) glu + LN + softmax
    ln_softmax_kernel<<<B_, U_>>>(gamma, beta);
    // (9) attention-weighted KAN reductions
    pq_kernel<<<dim3(B_, 16), 128>>>(x, tk);
    // (10) current = PQ @ Wc (16 splits, kChunk 72)
    {
        P4 Bb; Bb.p[0] = p_Wc; Bb.p[1] = p_Wc; Bb.p[2] = p_Wc; Bb.p[3] = p_Wc;
        O4 Cb; Cb.p[0] = p_cur; Cb.p[1] = p_cur; Cb.p[2] = p_cur; Cb.p[3] = p_cur;
        gemm64<<<dim3(4, 16, 1), 128>>>(p_PQ, 1152, 1.0f, p_PQ, 1152, 1152,
                                        0, 1152, 72, Bb, U_, Cb, U_);
    }
    // (11) LSTM gates: A = [cur/S , h_prev]; 4 gates fused (16 splits)
    {
        P4 Bb; Bb.p[0] = wf; Bb.p[1] = wi; Bb.p[2] = wc; Bb.p[3] = wo;
        O4 Cb; Cb.p[0] = p_gates; Cb.p[1] = p_gates + 32768;
        Cb.p[2] = p_gates + 65536; Cb.p[3] = p_gates + 98304;
        gemm64<<<dim3(4, 16, 4), 128>>>(p_cur, U_, 1.0f / (float)S_, h_prev, U_, U_,
                                        0, 2 * U_, 64, Bb, U_, Cb, U_);
    }
    // (12) LSTM elementwise
    final_kernel<<<(B_ * U_ + 255) / 256, 256>>>(c_prev, out);
}